// round 2
// baseline (speedup 1.0000x reference)
#include <cuda_runtime.h>
#include <math.h>
#include <stdint.h>

#define HD 32
#define MAXN 10000

// Scratch (device globals — no allocation allowed)
__device__ float g_z[MAXN * HD];
__device__ float g_u[MAXN * HD];
__device__ float g_v[MAXN * HD];
__device__ float g_m[MAXN * HD];   // holds max over edges of (v[s] + w*cw), -inf if none
__device__ float g_pa[MAXN];
__device__ float g_pb[MAXN];
__device__ float g_hsum[HD];

// fp32 atomic max via sign-aware integer atomics (exact, commutative -> deterministic)
__device__ __forceinline__ void atomicMaxF(float* addr, float v) {
    if (v >= 0.0f) atomicMax((int*)addr, __float_as_int(v));
    else           atomicMin((unsigned int*)addr, __float_as_uint(v));
}

// ---------------------------------------------------------------------------
// Fill p with -1e9 (the 400MB HBM-bound floor) — runs on a forked stream
// ---------------------------------------------------------------------------
__global__ void k_fill4(float4* __restrict__ p, size_t n4) {
    size_t i = (size_t)blockIdx.x * blockDim.x + threadIdx.x;
    size_t stride = (size_t)gridDim.x * blockDim.x;
    const float4 val = make_float4(-1e9f, -1e9f, -1e9f, -1e9f);
    for (; i < n4; i += stride) p[i] = val;
}
__global__ void k_fill1(float* __restrict__ p, size_t n) {
    size_t i = (size_t)blockIdx.x * blockDim.x + threadIdx.x;
    size_t stride = (size_t)gridDim.x * blockDim.x;
    for (; i < n; i += stride) p[i] = -1e9f;
}

// ---------------------------------------------------------------------------
// Encoder: z = [x,h]@W_enc + b_enc; u = z@W_msg[0:32], v = z@W_msg[32:64];
// init m = -inf; zero hsum. Warp per node, lane = feature. Grid-stride.
// ---------------------------------------------------------------------------
__global__ void k_encoder(const float* __restrict__ x, const float* __restrict__ h,
                          const float* __restrict__ W_enc, const float* __restrict__ b_enc,
                          const float* __restrict__ W_msg, int N) {
    __shared__ float sWe[33 * HD];
    __shared__ float sWm[64 * HD];
    int tid = threadIdx.x;
    for (int i = tid; i < 33 * HD; i += blockDim.x) sWe[i] = W_enc[i];
    for (int i = tid; i < 64 * HD; i += blockDim.x) sWm[i] = W_msg[i];
    if (blockIdx.x == 0 && tid < HD) g_hsum[tid] = 0.0f;
    __syncthreads();

    int lane = tid & 31;
    int wip  = tid >> 5;
    int warpsPerBlock = blockDim.x >> 5;
    int gridWarps = gridDim.x * warpsPerBlock;
    float be = b_enc[lane];

    for (int node = blockIdx.x * warpsPerBlock + wip; node < N; node += gridWarps) {
        float xn = x[node];
        float hl = h[node * HD + lane];
        // split z into two accumulators to shorten the dependent FMA chain
        float z0 = fmaf(xn, sWe[lane], be);
        float z1 = 0.0f;
#pragma unroll
        for (int k = 0; k < HD; k += 2) {
            float hk0 = __shfl_sync(0xffffffffu, hl, k);
            float hk1 = __shfl_sync(0xffffffffu, hl, k + 1);
            z0 = fmaf(hk0, sWe[(1 + k) * HD + lane], z0);
            z1 = fmaf(hk1, sWe[(2 + k) * HD + lane], z1);
        }
        float z = z0 + z1;
        g_z[node * HD + lane] = z;
        g_m[node * HD + lane] = __int_as_float(0xFF800000);  // -inf

        float u = 0.0f, v = 0.0f;
#pragma unroll
        for (int k = 0; k < HD; k++) {
            float zk = __shfl_sync(0xffffffffu, z, k);
            u = fmaf(zk, sWm[k * HD + lane], u);
            v = fmaf(zk, sWm[(HD + k) * HD + lane], v);
        }
        g_u[node * HD + lane] = u;
        g_v[node * HD + lane] = v;
    }
}

// ---------------------------------------------------------------------------
// Per-edge partial messages + scatter-max. Warp per edge, lane = feature.
// partial = v[s] + w*cw   (u[d] + b_msg is per-dest constant, added in k_update)
// Load-check before atomic: stale loads are only smaller, so skipping is safe.
// ---------------------------------------------------------------------------
__global__ void k_msg(const int* __restrict__ dests, const int* __restrict__ sources,
                      const float* __restrict__ weights,
                      const float* __restrict__ W_msg, int E) {
    int tid = threadIdx.x;
    int lane = tid & 31;
    int e = (int)((blockIdx.x * (size_t)blockDim.x + tid) >> 5);
    if (e >= E) return;
    float cw = W_msg[64 * HD + lane];
    int d = dests[e], s = sources[e];
    float w = weights[e];
    float cand = fmaf(w, cw, g_v[s * HD + lane]);
    float* addr = &g_m[d * HD + lane];
    float cur = *addr;
    if (cand > cur) atomicMaxF(addr, cand);
}

// ---------------------------------------------------------------------------
// Update + decode + pred-scalar precompute + hsum accumulation. Grid-stride.
// ---------------------------------------------------------------------------
__global__ void k_update(const float* __restrict__ W_upd, const float* __restrict__ b_upd,
                         const float* __restrict__ W_dec, const float* __restrict__ b_dec,
                         const float* __restrict__ W_pred, const float* __restrict__ b_msg,
                         float* __restrict__ out_y, float* __restrict__ out_h, int N) {
    __shared__ float sWu[64 * HD];
    __shared__ float red[8][HD];
    int tid = threadIdx.x;
    for (int i = tid; i < 64 * HD; i += blockDim.x) sWu[i] = W_upd[i];
    __syncthreads();

    int lane = tid & 31;
    int wip  = tid >> 5;
    int warpsPerBlock = blockDim.x >> 5;
    int gridWarps = gridDim.x * warpsPerBlock;
    float bu = b_upd[lane];
    float bm = b_msg[lane];
    float wd0 = W_dec[lane], wd1 = W_dec[HD + lane];
    float wp0 = W_pred[lane], wp1 = W_pred[HD + lane];
    float acc = 0.0f;  // per-warp partial sum of h_new for termination head

    for (int node = blockIdx.x * warpsPerBlock + wip; node < N; node += gridWarps) {
        float z = g_z[node * HD + lane];
        float u = g_u[node * HD + lane];
        float raw = g_m[node * HD + lane];
        float m = (raw == -INFINITY) ? 0.0f : (u + bm + raw);

        // two accumulators (z-part and m-part) to halve dependent latency
        float h0 = bu, h1 = 0.0f;
#pragma unroll
        for (int k = 0; k < HD; k++) {
            float zk = __shfl_sync(0xffffffffu, z, k);
            float mk = __shfl_sync(0xffffffffu, m, k);
            h0 = fmaf(zk, sWu[k * HD + lane], h0);
            h1 = fmaf(mk, sWu[(HD + k) * HD + lane], h1);
        }
        float hn = h0 + h1;
        out_h[node * HD + lane] = hn;
        acc += hn;

        float ry = fmaf(z, wd0, hn * wd1);
        float ra = hn * wp0;
        float rb = hn * wp1;
#pragma unroll
        for (int o = 16; o > 0; o >>= 1) {
            ry += __shfl_xor_sync(0xffffffffu, ry, o);
            ra += __shfl_xor_sync(0xffffffffu, ra, o);
            rb += __shfl_xor_sync(0xffffffffu, rb, o);
        }
        if (lane == 0) {
            out_y[node] = ry + b_dec[0];
            g_pa[node] = ra;
            g_pb[node] = rb;
        }
    }

    red[wip][lane] = acc;
    __syncthreads();
    if (wip == 0) {
        float s = red[0][lane];
#pragma unroll
        for (int j = 1; j < 8; j++) s += red[j][lane];
        atomicAdd(&g_hsum[lane], s);
    }
}

// ---------------------------------------------------------------------------
// Termination scalar: t = (mean(h_new) @ W_term + b_term)
// ---------------------------------------------------------------------------
__global__ void k_t(const float* __restrict__ W_term, const float* __restrict__ b_term,
                    float* __restrict__ out_t, int N) {
    int lane = threadIdx.x;
    float v = (g_hsum[lane] / (float)N) * W_term[lane];
#pragma unroll
    for (int o = 16; o > 0; o >>= 1) v += __shfl_xor_sync(0xffffffffu, v, o);
    if (lane == 0) out_t[0] = v + b_term[0];
}

// ---------------------------------------------------------------------------
// Predecessor edge scores scattered into p. Thread per edge.
// ---------------------------------------------------------------------------
__global__ void k_pred(const int* __restrict__ dests, const int* __restrict__ sources,
                       const float* __restrict__ weights,
                       const float* __restrict__ W_pred, const float* __restrict__ b_pred,
                       float* __restrict__ p, int N, int E) {
    int e = blockIdx.x * blockDim.x + threadIdx.x;
    if (e >= E) return;
    int d = dests[e], s = sources[e];
    float sc = g_pa[d] + g_pb[s] + fmaf(weights[e], W_pred[64], b_pred[0]);
    p[(size_t)d * N + s] = sc;
}

// ---------------------------------------------------------------------------
extern "C" void kernel_launch(void* const* d_in, const int* in_sizes, int n_in,
                              void* d_out, int out_size) {
    const int*   sources = (const int*)d_in[0];
    const int*   dests   = (const int*)d_in[1];
    const float* weights = (const float*)d_in[2];
    const float* x       = (const float*)d_in[3];
    const float* h       = (const float*)d_in[4];
    const float* W_enc   = (const float*)d_in[5];
    const float* b_enc   = (const float*)d_in[6];
    const float* W_msg   = (const float*)d_in[7];
    const float* b_msg   = (const float*)d_in[8];
    const float* W_upd   = (const float*)d_in[9];
    const float* b_upd   = (const float*)d_in[10];
    const float* W_dec   = (const float*)d_in[11];
    const float* b_dec   = (const float*)d_in[12];
    const float* W_term  = (const float*)d_in[13];
    const float* b_term  = (const float*)d_in[14];
    const float* W_pred  = (const float*)d_in[15];
    const float* b_pred  = (const float*)d_in[16];

    int E = in_sizes[0];
    int N = in_sizes[3];  // x is (N, 1)

    float* out   = (float*)d_out;
    float* out_y = out;
    float* out_p = out + N;
    float* out_h = out + N + (size_t)N * N;
    float* out_t = out_h + (size_t)N * HD;

    // One-time infra: side stream + fork/join events (no device memory involved)
    static cudaStream_t s_fill = nullptr;
    static cudaEvent_t ev_fork = nullptr, ev_join = nullptr;
    if (s_fill == nullptr) {
        cudaStreamCreateWithFlags(&s_fill, cudaStreamNonBlocking);
        cudaEventCreateWithFlags(&ev_fork, cudaEventDisableTiming);
        cudaEventCreateWithFlags(&ev_join, cudaEventDisableTiming);
    }

    // Fork: run the 400MB fill concurrently with the compute chain
    cudaEventRecord(ev_fork, 0);
    cudaStreamWaitEvent(s_fill, ev_fork, 0);
    size_t nn = (size_t)N * N;
    if ((((uintptr_t)out_p) & 15) == 0 && (nn & 3) == 0) {
        k_fill4<<<4736, 256, 0, s_fill>>>((float4*)out_p, nn / 4);
    } else {
        k_fill1<<<4736, 256, 0, s_fill>>>(out_p, nn);
    }
    cudaEventRecord(ev_join, s_fill);

    // Compute chain on the main (captured) stream
    int nodeBlocks = 296;                  // grid-stride, 8 warps/block
    int edgeWarpBlocks = (E + 7) / 8;      // warp per edge
    k_encoder<<<nodeBlocks, 256>>>(x, h, W_enc, b_enc, W_msg, N);
    k_msg<<<edgeWarpBlocks, 256>>>(dests, sources, weights, W_msg, E);
    k_update<<<nodeBlocks, 256>>>(W_upd, b_upd, W_dec, b_dec, W_pred, b_msg, out_y, out_h, N);
    k_t<<<1, 32>>>(W_term, b_term, out_t, N);

    // Join: pred scatter must come after both the fill and the update
    cudaStreamWaitEvent(0, ev_join, 0);
    k_pred<<<(E + 255) / 256, 256>>>(dests, sources, weights, W_pred, b_pred, out_p, N, E);
}

// round 3
// speedup vs baseline: 1.3603x; 1.3603x over previous
#include <cuda_runtime.h>
#include <math.h>
#include <stdint.h>

#define HD 32
#define MAXN 10000
#define CAP 256   // max in-degree supported (E/N = 32 expected, Poisson tail << 256)

// Scratch (device globals — no allocation allowed)
__device__ float g_z[MAXN * HD];
__device__ float g_u[MAXN * HD];
__device__ float g_v[MAXN * HD];
__device__ float g_pa[MAXN];
__device__ float g_pb[MAXN];
__device__ float g_hsum[HD];
__device__ int   g_cnt[MAXN];
__device__ int   g_list[MAXN * CAP];

// ---------------------------------------------------------------------------
// Zero per-dest counters and hsum
// ---------------------------------------------------------------------------
__global__ void k_init(int N) {
    int i = blockIdx.x * blockDim.x + threadIdx.x;
    if (i < N) g_cnt[i] = 0;
    if (i < HD) g_hsum[i] = 0.0f;
}

// ---------------------------------------------------------------------------
// Build per-dest edge lists (fixed capacity). 320K int atomics over 10K addrs.
// ---------------------------------------------------------------------------
__global__ void k_build(const int* __restrict__ dests, int E) {
    int e = blockIdx.x * blockDim.x + threadIdx.x;
    if (e >= E) return;
    int d = dests[e];
    int slot = atomicAdd(&g_cnt[d], 1);
    if (slot < CAP) g_list[d * CAP + slot] = e;
}

// ---------------------------------------------------------------------------
// Encoder: z = [x,h]@W_enc + b_enc; u = z@W_msg[0:32], v = z@W_msg[32:64].
// Warp per node, lane = feature.
// ---------------------------------------------------------------------------
__global__ void k_encoder(const float* __restrict__ x, const float* __restrict__ h,
                          const float* __restrict__ W_enc, const float* __restrict__ b_enc,
                          const float* __restrict__ W_msg, int N) {
    __shared__ float sWe[33 * HD];
    __shared__ float sWm[64 * HD];
    int tid = threadIdx.x;
    for (int i = tid; i < 33 * HD; i += blockDim.x) sWe[i] = W_enc[i];
    for (int i = tid; i < 64 * HD; i += blockDim.x) sWm[i] = W_msg[i];
    __syncthreads();

    int lane = tid & 31;
    int node = (int)((blockIdx.x * (size_t)blockDim.x + tid) >> 5);
    if (node >= N) return;

    float xn = x[node];
    float hl = h[node * HD + lane];
    float z0 = fmaf(xn, sWe[lane], b_enc[lane]);
    float z1 = 0.0f;
#pragma unroll
    for (int k = 0; k < HD; k += 2) {
        float hk0 = __shfl_sync(0xffffffffu, hl, k);
        float hk1 = __shfl_sync(0xffffffffu, hl, k + 1);
        z0 = fmaf(hk0, sWe[(1 + k) * HD + lane], z0);
        z1 = fmaf(hk1, sWe[(2 + k) * HD + lane], z1);
    }
    float z = z0 + z1;
    g_z[node * HD + lane] = z;

    float u = 0.0f, v = 0.0f;
#pragma unroll
    for (int k = 0; k < HD; k++) {
        float zk = __shfl_sync(0xffffffffu, z, k);
        u = fmaf(zk, sWm[k * HD + lane], u);
        v = fmaf(zk, sWm[(HD + k) * HD + lane], v);
    }
    g_u[node * HD + lane] = u;
    g_v[node * HD + lane] = v;
}

// ---------------------------------------------------------------------------
// Fused: segment-max over incoming edges (atomic-free) + update + decode +
// pred scalars + hsum. Warp per node, lane = feature.
// message = u[d] + v[s] + w*cw + b_msg; max over edges = (u[d]+b_msg) + max(v[s]+w*cw)
// ---------------------------------------------------------------------------
__global__ void k_update(const int* __restrict__ sources, const float* __restrict__ weights,
                         const float* __restrict__ W_msg, const float* __restrict__ b_msg,
                         const float* __restrict__ W_upd, const float* __restrict__ b_upd,
                         const float* __restrict__ W_dec, const float* __restrict__ b_dec,
                         const float* __restrict__ W_pred,
                         float* __restrict__ out_y, float* __restrict__ out_h, int N) {
    __shared__ float sWu[64 * HD];
    __shared__ float red[8][HD];
    int tid = threadIdx.x;
    for (int i = tid; i < 64 * HD; i += blockDim.x) sWu[i] = W_upd[i];
    __syncthreads();

    int lane = tid & 31;
    int wip  = tid >> 5;
    int node = (int)((blockIdx.x * (size_t)blockDim.x + tid) >> 5);
    bool act = node < N;
    float hn = 0.0f;

    if (act) {
        float cw = W_msg[64 * HD + lane];
        int cnt = min(g_cnt[node], CAP);
        const int* lst = &g_list[node * CAP];

        // segment max of (v[s] + w*cw) over incoming edges — no atomics
        float mraw = __int_as_float(0xFF800000);  // -inf
        for (int i = 0; i < cnt; i++) {
            int e = lst[i];                 // broadcast load (same addr all lanes)
            int s = sources[e];
            float w = weights[e];
            mraw = fmaxf(mraw, fmaf(w, cw, g_v[s * HD + lane]));
        }
        float z = g_z[node * HD + lane];
        float m = (cnt == 0) ? 0.0f
                             : (g_u[node * HD + lane] + b_msg[lane] + mraw);

        float h0 = b_upd[lane], h1 = 0.0f;
#pragma unroll
        for (int k = 0; k < HD; k++) {
            float zk = __shfl_sync(0xffffffffu, z, k);
            float mk = __shfl_sync(0xffffffffu, m, k);
            h0 = fmaf(zk, sWu[k * HD + lane], h0);
            h1 = fmaf(mk, sWu[(HD + k) * HD + lane], h1);
        }
        hn = h0 + h1;
        out_h[node * HD + lane] = hn;

        float ry = fmaf(z, W_dec[lane], hn * W_dec[HD + lane]);
        float ra = hn * W_pred[lane];
        float rb = hn * W_pred[HD + lane];
#pragma unroll
        for (int o = 16; o > 0; o >>= 1) {
            ry += __shfl_xor_sync(0xffffffffu, ry, o);
            ra += __shfl_xor_sync(0xffffffffu, ra, o);
            rb += __shfl_xor_sync(0xffffffffu, rb, o);
        }
        if (lane == 0) {
            out_y[node] = ry + b_dec[0];
            g_pa[node] = ra;
            g_pb[node] = rb;
        }
    }

    red[wip][lane] = act ? hn : 0.0f;
    __syncthreads();
    if (wip == 0) {
        float s = red[0][lane];
#pragma unroll
        for (int j = 1; j < 8; j++) s += red[j][lane];
        atomicAdd(&g_hsum[lane], s);
    }
}

// ---------------------------------------------------------------------------
// Termination scalar: t = (mean(h_new) @ W_term + b_term)
// ---------------------------------------------------------------------------
__global__ void k_t(const float* __restrict__ W_term, const float* __restrict__ b_term,
                    float* __restrict__ out_t, int N) {
    int lane = threadIdx.x;
    float v = (g_hsum[lane] / (float)N) * W_term[lane];
#pragma unroll
    for (int o = 16; o > 0; o >>= 1) v += __shfl_xor_sync(0xffffffffu, v, o);
    if (lane == 0) out_t[0] = v + b_term[0];
}

// ---------------------------------------------------------------------------
// Fused row fill + edge-score scatter: one block per row of p.
// Writes each row exactly once: -1e9 everywhere, then edge cells overwritten.
// ---------------------------------------------------------------------------
__global__ void k_rowfill(const int* __restrict__ sources, const float* __restrict__ weights,
                          const float* __restrict__ W_pred, const float* __restrict__ b_pred,
                          float* __restrict__ p, int N) {
    int d = blockIdx.x;
    float* row = p + (size_t)d * N;
    int n4 = N >> 2;
    const float4 val = make_float4(-1e9f, -1e9f, -1e9f, -1e9f);
    float4* row4 = (float4*)row;
    for (int i = threadIdx.x; i < n4; i += blockDim.x) row4[i] = val;
    for (int i = (n4 << 2) + threadIdx.x; i < N; i += blockDim.x) row[i] = -1e9f;
    __syncthreads();

    int cnt = min(g_cnt[d], CAP);
    if (threadIdx.x < cnt) {
        float pa = g_pa[d];
        float c  = W_pred[64];
        float b0 = b_pred[0];
        for (int i = threadIdx.x; i < cnt; i += blockDim.x) {
            int e = g_list[d * CAP + i];
            int s = sources[e];
            row[s] = pa + g_pb[s] + fmaf(weights[e], c, b0);
        }
    }
}

// ---------------------------------------------------------------------------
extern "C" void kernel_launch(void* const* d_in, const int* in_sizes, int n_in,
                              void* d_out, int out_size) {
    const int*   sources = (const int*)d_in[0];
    const int*   dests   = (const int*)d_in[1];
    const float* weights = (const float*)d_in[2];
    const float* x       = (const float*)d_in[3];
    const float* h       = (const float*)d_in[4];
    const float* W_enc   = (const float*)d_in[5];
    const float* b_enc   = (const float*)d_in[6];
    const float* W_msg   = (const float*)d_in[7];
    const float* b_msg   = (const float*)d_in[8];
    const float* W_upd   = (const float*)d_in[9];
    const float* b_upd   = (const float*)d_in[10];
    const float* W_dec   = (const float*)d_in[11];
    const float* b_dec   = (const float*)d_in[12];
    const float* W_term  = (const float*)d_in[13];
    const float* b_term  = (const float*)d_in[14];
    const float* W_pred  = (const float*)d_in[15];
    const float* b_pred  = (const float*)d_in[16];

    int E = in_sizes[0];
    int N = in_sizes[3];  // x is (N, 1)

    float* out   = (float*)d_out;
    float* out_y = out;
    float* out_p = out + N;
    float* out_h = out + N + (size_t)N * N;
    float* out_t = out_h + (size_t)N * HD;

    int nodeBlocks = (N * 32 + 255) / 256;   // warp per node

    k_init<<<(N + 255) / 256, 256>>>(N);
    k_build<<<(E + 255) / 256, 256>>>(dests, E);
    k_encoder<<<nodeBlocks, 256>>>(x, h, W_enc, b_enc, W_msg, N);
    k_update<<<nodeBlocks, 256>>>(sources, weights, W_msg, b_msg, W_upd, b_upd,
                                  W_dec, b_dec, W_pred, out_y, out_h, N);
    k_t<<<1, 32>>>(W_term, b_term, out_t, N);
    k_rowfill<<<N, 256>>>(sources, weights, W_pred, b_pred, out_p, N);
}

// round 4
// speedup vs baseline: 1.4248x; 1.0474x over previous
#include <cuda_runtime.h>
#include <math.h>
#include <stdint.h>

#define HD 32
#define MAXN 10000
#define CAP 256   // max in-degree supported (E/N = 32 mean, Poisson tail << 256)

// Scratch (device globals — no allocation allowed)
__device__ float g_z[MAXN * HD];
__device__ float g_u[MAXN * HD];
__device__ float g_v[MAXN * HD];
__device__ float g_pa[MAXN];
__device__ float g_pb[MAXN];
__device__ float g_hsum[HD];
__device__ int   g_cnt[MAXN];
__device__ int   g_list[MAXN * CAP];

// ---------------------------------------------------------------------------
// Fill p with -1e9. Limited grid (4 blocks/SM) so chain kernels co-schedule.
// ---------------------------------------------------------------------------
__global__ void k_fill4(float4* __restrict__ p, size_t n4) {
    size_t i = (size_t)blockIdx.x * blockDim.x + threadIdx.x;
    size_t stride = (size_t)gridDim.x * blockDim.x;
    const float4 val = make_float4(-1e9f, -1e9f, -1e9f, -1e9f);
    for (; i < n4; i += stride) p[i] = val;
}
__global__ void k_fill1(float* __restrict__ p, size_t n) {
    size_t i = (size_t)blockIdx.x * blockDim.x + threadIdx.x;
    size_t stride = (size_t)gridDim.x * blockDim.x;
    for (; i < n; i += stride) p[i] = -1e9f;
}

// ---------------------------------------------------------------------------
// Zero per-dest counters and hsum
// ---------------------------------------------------------------------------
__global__ void k_init(int N) {
    int i = blockIdx.x * blockDim.x + threadIdx.x;
    if (i < N) g_cnt[i] = 0;
    if (i < HD) g_hsum[i] = 0.0f;
}

// ---------------------------------------------------------------------------
// Build per-dest edge lists (fixed capacity)
// ---------------------------------------------------------------------------
__global__ void k_build(const int* __restrict__ dests, int E) {
    int e = blockIdx.x * blockDim.x + threadIdx.x;
    if (e >= E) return;
    int d = dests[e];
    int slot = atomicAdd(&g_cnt[d], 1);
    if (slot < CAP) g_list[d * CAP + slot] = e;
}

// ---------------------------------------------------------------------------
// Encoder: z = [x,h]@W_enc + b_enc; u = z@W_msg[0:32], v = z@W_msg[32:64].
// Warp per node, lane = feature.
// ---------------------------------------------------------------------------
__global__ void k_encoder(const float* __restrict__ x, const float* __restrict__ h,
                          const float* __restrict__ W_enc, const float* __restrict__ b_enc,
                          const float* __restrict__ W_msg, int N) {
    __shared__ float sWe[33 * HD];
    __shared__ float sWm[64 * HD];
    int tid = threadIdx.x;
    for (int i = tid; i < 33 * HD; i += blockDim.x) sWe[i] = W_enc[i];
    for (int i = tid; i < 64 * HD; i += blockDim.x) sWm[i] = W_msg[i];
    __syncthreads();

    int lane = tid & 31;
    int node = (int)((blockIdx.x * (size_t)blockDim.x + tid) >> 5);
    if (node >= N) return;

    float xn = x[node];
    float hl = h[node * HD + lane];
    float z0 = fmaf(xn, sWe[lane], b_enc[lane]);
    float z1 = 0.0f;
#pragma unroll
    for (int k = 0; k < HD; k += 2) {
        float hk0 = __shfl_sync(0xffffffffu, hl, k);
        float hk1 = __shfl_sync(0xffffffffu, hl, k + 1);
        z0 = fmaf(hk0, sWe[(1 + k) * HD + lane], z0);
        z1 = fmaf(hk1, sWe[(2 + k) * HD + lane], z1);
    }
    float z = z0 + z1;
    g_z[node * HD + lane] = z;

    float u = 0.0f, v = 0.0f;
#pragma unroll
    for (int k = 0; k < HD; k++) {
        float zk = __shfl_sync(0xffffffffu, z, k);
        u = fmaf(zk, sWm[k * HD + lane], u);
        v = fmaf(zk, sWm[(HD + k) * HD + lane], v);
    }
    g_u[node * HD + lane] = u;
    g_v[node * HD + lane] = v;
}

// ---------------------------------------------------------------------------
// Fused: segment-max (atomic-free, lane-parallel edge loads + shuffle bcast,
// 4x-unrolled v-row gathers for MLP) + update + decode + pred scalars + hsum.
// Warp per node, lane = feature.
// ---------------------------------------------------------------------------
__global__ void k_update(const int* __restrict__ sources, const float* __restrict__ weights,
                         const float* __restrict__ W_msg, const float* __restrict__ b_msg,
                         const float* __restrict__ W_upd, const float* __restrict__ b_upd,
                         const float* __restrict__ W_dec, const float* __restrict__ b_dec,
                         const float* __restrict__ W_pred,
                         float* __restrict__ out_y, float* __restrict__ out_h, int N) {
    __shared__ float sWu[64 * HD];
    __shared__ float red[8][HD];
    int tid = threadIdx.x;
    for (int i = tid; i < 64 * HD; i += blockDim.x) sWu[i] = W_upd[i];
    __syncthreads();

    int lane = tid & 31;
    int wip  = tid >> 5;
    int node = (int)((blockIdx.x * (size_t)blockDim.x + tid) >> 5);
    bool act = node < N;
    float hn = 0.0f;

    if (act) {
        float cw = W_msg[64 * HD + lane];
        int cnt = min(g_cnt[node], CAP);
        const int* lst = &g_list[node * CAP];

        float mraw = __int_as_float(0xFF800000);  // -inf
        for (int base = 0; base < cnt; base += 32) {
            int nrem = min(32, cnt - base);
            // lane-parallel: each lane fetches one edge's (s, w)
            int   myS = 0;
            float myW = 0.0f;
            if (lane < nrem) {
                int e = lst[base + lane];     // coalesced
                myS = sources[e];
                myW = weights[e];
            }
            int k = 0;
            for (; k + 4 <= nrem; k += 4) {
                int   s0 = __shfl_sync(0xffffffffu, myS, k);
                int   s1 = __shfl_sync(0xffffffffu, myS, k + 1);
                int   s2 = __shfl_sync(0xffffffffu, myS, k + 2);
                int   s3 = __shfl_sync(0xffffffffu, myS, k + 3);
                float w0 = __shfl_sync(0xffffffffu, myW, k);
                float w1 = __shfl_sync(0xffffffffu, myW, k + 1);
                float w2 = __shfl_sync(0xffffffffu, myW, k + 2);
                float w3 = __shfl_sync(0xffffffffu, myW, k + 3);
                float v0 = g_v[s0 * HD + lane];   // 4 independent gathers -> MLP 4
                float v1 = g_v[s1 * HD + lane];
                float v2 = g_v[s2 * HD + lane];
                float v3 = g_v[s3 * HD + lane];
                float a = fmaxf(fmaf(w0, cw, v0), fmaf(w1, cw, v1));
                float b = fmaxf(fmaf(w2, cw, v2), fmaf(w3, cw, v3));
                mraw = fmaxf(mraw, fmaxf(a, b));
            }
            for (; k < nrem; k++) {
                int   sk = __shfl_sync(0xffffffffu, myS, k);
                float wk = __shfl_sync(0xffffffffu, myW, k);
                mraw = fmaxf(mraw, fmaf(wk, cw, g_v[sk * HD + lane]));
            }
        }

        float z = g_z[node * HD + lane];
        float m = (cnt == 0) ? 0.0f
                             : (g_u[node * HD + lane] + b_msg[lane] + mraw);

        float h0 = b_upd[lane], h1 = 0.0f;
#pragma unroll
        for (int k = 0; k < HD; k++) {
            float zk = __shfl_sync(0xffffffffu, z, k);
            float mk = __shfl_sync(0xffffffffu, m, k);
            h0 = fmaf(zk, sWu[k * HD + lane], h0);
            h1 = fmaf(mk, sWu[(HD + k) * HD + lane], h1);
        }
        hn = h0 + h1;
        out_h[node * HD + lane] = hn;

        float ry = fmaf(z, W_dec[lane], hn * W_dec[HD + lane]);
        float ra = hn * W_pred[lane];
        float rb = hn * W_pred[HD + lane];
#pragma unroll
        for (int o = 16; o > 0; o >>= 1) {
            ry += __shfl_xor_sync(0xffffffffu, ry, o);
            ra += __shfl_xor_sync(0xffffffffu, ra, o);
            rb += __shfl_xor_sync(0xffffffffu, rb, o);
        }
        if (lane == 0) {
            out_y[node] = ry + b_dec[0];
            g_pa[node] = ra;
            g_pb[node] = rb;
        }
    }

    red[wip][lane] = act ? hn : 0.0f;
    __syncthreads();
    if (wip == 0) {
        float s = red[0][lane];
#pragma unroll
        for (int j = 1; j < 8; j++) s += red[j][lane];
        atomicAdd(&g_hsum[lane], s);
    }
}

// ---------------------------------------------------------------------------
// Termination scalar: t = (mean(h_new) @ W_term + b_term)
// ---------------------------------------------------------------------------
__global__ void k_t(const float* __restrict__ W_term, const float* __restrict__ b_term,
                    float* __restrict__ out_t, int N) {
    int lane = threadIdx.x;
    float v = (g_hsum[lane] / (float)N) * W_term[lane];
#pragma unroll
    for (int o = 16; o > 0; o >>= 1) v += __shfl_xor_sync(0xffffffffu, v, o);
    if (lane == 0) out_t[0] = v + b_term[0];
}

// ---------------------------------------------------------------------------
// Predecessor edge scores scattered into p. Thread per edge.
// ---------------------------------------------------------------------------
__global__ void k_pred(const int* __restrict__ dests, const int* __restrict__ sources,
                       const float* __restrict__ weights,
                       const float* __restrict__ W_pred, const float* __restrict__ b_pred,
                       float* __restrict__ p, int N, int E) {
    int e = blockIdx.x * blockDim.x + threadIdx.x;
    if (e >= E) return;
    int d = dests[e], s = sources[e];
    float sc = g_pa[d] + g_pb[s] + fmaf(weights[e], W_pred[64], b_pred[0]);
    p[(size_t)d * N + s] = sc;
}

// ---------------------------------------------------------------------------
extern "C" void kernel_launch(void* const* d_in, const int* in_sizes, int n_in,
                              void* d_out, int out_size) {
    const int*   sources = (const int*)d_in[0];
    const int*   dests   = (const int*)d_in[1];
    const float* weights = (const float*)d_in[2];
    const float* x       = (const float*)d_in[3];
    const float* h       = (const float*)d_in[4];
    const float* W_enc   = (const float*)d_in[5];
    const float* b_enc   = (const float*)d_in[6];
    const float* W_msg   = (const float*)d_in[7];
    const float* b_msg   = (const float*)d_in[8];
    const float* W_upd   = (const float*)d_in[9];
    const float* b_upd   = (const float*)d_in[10];
    const float* W_dec   = (const float*)d_in[11];
    const float* b_dec   = (const float*)d_in[12];
    const float* W_term  = (const float*)d_in[13];
    const float* b_term  = (const float*)d_in[14];
    const float* W_pred  = (const float*)d_in[15];
    const float* b_pred  = (const float*)d_in[16];

    int E = in_sizes[0];
    int N = in_sizes[3];  // x is (N, 1)

    float* out   = (float*)d_out;
    float* out_y = out;
    float* out_p = out + N;
    float* out_h = out + N + (size_t)N * N;
    float* out_t = out_h + (size_t)N * HD;

    // One-time infra: side stream + fork/join events
    static cudaStream_t s_fill = nullptr;
    static cudaEvent_t ev_fork = nullptr, ev_join = nullptr;
    if (s_fill == nullptr) {
        cudaStreamCreateWithFlags(&s_fill, cudaStreamNonBlocking);
        cudaEventCreateWithFlags(&ev_fork, cudaEventDisableTiming);
        cudaEventCreateWithFlags(&ev_join, cudaEventDisableTiming);
    }

    // Fork: 400MB fill on side stream with LIMITED grid (4 blocks/SM) so the
    // latency-bound chain co-schedules on the remaining warp slots.
    cudaEventRecord(ev_fork, 0);
    cudaStreamWaitEvent(s_fill, ev_fork, 0);
    size_t nn = (size_t)N * N;
    if ((((uintptr_t)out_p) & 15) == 0 && (nn & 3) == 0) {
        k_fill4<<<592, 256, 0, s_fill>>>((float4*)out_p, nn / 4);
    } else {
        k_fill1<<<592, 256, 0, s_fill>>>(out_p, nn);
    }
    cudaEventRecord(ev_join, s_fill);

    // Compute chain on the main stream (co-resident with the fill)
    int nodeBlocks = (N * 32 + 255) / 256;   // warp per node
    k_init<<<(N + 255) / 256, 256>>>(N);
    k_build<<<(E + 255) / 256, 256>>>(dests, E);
    k_encoder<<<nodeBlocks, 256>>>(x, h, W_enc, b_enc, W_msg, N);
    k_update<<<nodeBlocks, 256>>>(sources, weights, W_msg, b_msg, W_upd, b_upd,
                                  W_dec, b_dec, W_pred, out_y, out_h, N);
    k_t<<<1, 32>>>(W_term, b_term, out_t, N);

    // Join: edge-score scatter needs both the fill and g_pa/g_pb
    cudaStreamWaitEvent(0, ev_join, 0);
    k_pred<<<(E + 255) / 256, 256>>>(dests, sources, weights, W_pred, b_pred, out_p, N, E);
}